// round 6
// baseline (speedup 1.0000x reference)
#include <cuda_runtime.h>

// ---------------------------------------------------------------------------
// MultiLevelClassifier — routed experts, round 3.
//
// R2 ncu: gemm kernels latency-bound (DRAM 8.8%, issue 36%, scalar LDG.32
// weight loads, 63 regs). This round: 2 cols/thread with LDG.64 weight
// loads (weights arrive pre-packed for fma.f32x2), block split into 2
// f-subgroups (split-K depth 16), acc down to 16 regs -> ~6 blocks/SM,
// R=16 for levels 1/2 to halve weight re-reads.
// ---------------------------------------------------------------------------

#define BB   1024
#define FF   1024
#define EE   256
#define L1C  16
#define L2C  8
#define L3C  32
#define NE3  128
#define FSEG 8              // grid.y f-segments
#define FS   (FF / FSEG)    // 128 features per block
#define SEGS (FSEG * 2)     // split-K depth incl. in-block subgroups

// scratch (device globals — no allocation allowed)
__device__ int   g_cnt2[L1C];
__device__ int   g_cnt3[NE3];
__device__ int   g_rows2[L1C * BB];
__device__ int   g_rows3[NE3 * BB];
__device__ float g_part[SEGS * BB * EE];   // 16 MB split-K partials

// ---- packed f32x2 helpers (sm_103a) ---------------------------------------
__device__ __forceinline__ unsigned long long pack2f(float a, float b) {
    unsigned long long r;
    asm("mov.b64 %0, {%1, %2};" : "=l"(r) : "f"(a), "f"(b));
    return r;
}
__device__ __forceinline__ void fma_f32x2(unsigned long long& d,
                                          unsigned long long a,
                                          unsigned long long b) {
    asm("fma.rn.f32x2 %0, %1, %2, %0;" : "+l"(d) : "l"(a), "l"(b));
}
__device__ __forceinline__ float2 unpack2(unsigned long long v) {
    float2 r;
    asm("mov.b64 {%0, %1}, %2;" : "=f"(r.x), "=f"(r.y) : "l"(v));
    return r;
}

// ---------------------------------------------------------------------------
__global__ void k_init() {
    int t = threadIdx.x;
    if (t < L1C) g_cnt2[t] = 0;
    if (t < NE3) g_cnt3[t] = 0;
}

// ---------------------------------------------------------------------------
// Split-K GEMM. Block (slot, seg, expert). 256 threads:
//   sub = tid>>7 (f-subgroup, 64 features each), ct = tid&127 -> columns
//   2ct, 2ct+1. Weights load as float2 (LDG.64) and feed fma.f32x2 directly.
// Partials written to g_part[seg*2+sub][row][col] as float2.
// ---------------------------------------------------------------------------
template <int R, bool MIX, bool DENSE>
__global__ __launch_bounds__(256) void k_gemm(
    const float* __restrict__ fx, const float* __restrict__ fy,
    const float* __restrict__ W1base,          // [NEXP][FF][EE]
    const int* __restrict__ rowlists,
    const int* __restrict__ cnts)
{
    const int tid  = threadIdx.x;
    const int sub  = tid >> 7;          // 0,1
    const int ct   = tid & 127;         // column pair
    const int slot = blockIdx.x, nslot = gridDim.x;
    const int seg  = blockIdx.y;
    const int e    = blockIdx.z;
    const int fbase = seg * FS;                 // block feature base
    const int cnt  = DENSE ? BB : cnts[e];
    const float* __restrict__ W1 =
        W1base + (size_t)e * FF * EE + (size_t)(fbase + sub * (FS / 2)) * EE + 2 * ct;

    __shared__ float feat[R][FS];

    for (int c = slot; c * R < cnt; c += nslot) {
        const int start = c * R;
        const int nr = min(R, cnt - start);
        const int* rowids = DENSE ? nullptr : (rowlists + e * BB + start);

        // ---- cooperative feature-segment load ---------------------------
        #pragma unroll
        for (int i = tid; i < R * FS / 4; i += 256) {
            int r  = i / (FS / 4);
            int j  = (i % (FS / 4)) * 4;
            int rr = (r < nr) ? r : 0;
            int b  = DENSE ? (start + rr) : rowids[rr];
            float4 v = *(const float4*)(fx + (size_t)b * FF + fbase + j);
            if (MIX) {
                float4 u = *(const float4*)(fy + (size_t)b * FF + fbase + j);
                v.x = 0.6f * v.x + 0.4f * u.x;
                v.y = 0.6f * v.y + 0.4f * u.y;
                v.z = 0.6f * v.z + 0.4f * u.z;
                v.w = 0.6f * v.w + 0.4f * u.w;
            }
            *(float4*)&feat[r][j] = v;
        }
        __syncthreads();

        // ---- GEMM: 64 f per subgroup, 2 cols per thread -----------------
        unsigned long long acc[R];
        #pragma unroll
        for (int r = 0; r < R; r++) acc[r] = 0ull;

        const float* fptr = &feat[0][sub * (FS / 2)];
        #pragma unroll 4
        for (int f = 0; f < FS / 2; f++) {
            float2 w = *(const float2*)(W1 + (size_t)f * EE);
            unsigned long long wv = pack2f(w.x, w.y);
            #pragma unroll
            for (int r = 0; r < R; r++) {
                float fv = fptr[r * FS + f];
                fma_f32x2(acc[r], pack2f(fv, fv), wv);
            }
        }

        // ---- write partials (float2, coalesced) -------------------------
        const int sidx = seg * 2 + sub;
        #pragma unroll
        for (int r = 0; r < R; r++) {
            if (r < nr) {
                int b = DENSE ? (start + r) : rowids[r];
                *(float2*)&g_part[((size_t)sidx * BB + b) * EE + 2 * ct] =
                    unpack2(acc[r]);
            }
        }
        __syncthreads();
    }
}

// ---------------------------------------------------------------------------
// Finish: reduce SEGS partials -> LN -> ReLU -> x W2 + b2 -> logits,
// argmax -> scatter to next-level routing lists.
// ---------------------------------------------------------------------------
template <int R, int L, bool DENSE>
__global__ __launch_bounds__(256) void k_fin(
    const int* __restrict__ rowlists, const int* __restrict__ cnts,
    const float* __restrict__ gbase, const float* __restrict__ bbase,
    const float* __restrict__ W2base, const float* __restrict__ b2base,
    float* __restrict__ logits_out,
    int* __restrict__ cnt_next, int* __restrict__ rows_next)
{
    const int tid  = threadIdx.x;
    const int slot = blockIdx.x, nslot = gridDim.x;
    const int e    = blockIdx.y;
    const int cnt  = DENSE ? BB : cnts[e];

    const float* __restrict__ gg = gbase  + (size_t)e * EE;
    const float* __restrict__ bv = bbase  + (size_t)e * EE;
    const float* __restrict__ W2 = W2base + (size_t)e * EE * L;
    const float* __restrict__ b2 = b2base + (size_t)e * L;

    __shared__ float act[R][EE];
    __shared__ float reds[R][8], redq[R][8];
    __shared__ float mean[R], rstd[R];
    __shared__ float lg[R][32];

    const int lane = tid & 31, wid = tid >> 5;
    const float gt = gg[tid], bt = bv[tid];

    for (int c = slot; c * R < cnt; c += nslot) {
        const int start = c * R;
        const int nr = min(R, cnt - start);
        const int* rowids = DENSE ? nullptr : (rowlists + e * BB + start);

        // ---- reduce split-K partials ------------------------------------
        float h[R];
        #pragma unroll
        for (int r = 0; r < R; r++) {
            int rr = (r < nr) ? r : 0;
            int b  = DENSE ? (start + rr) : rowids[rr];
            float s = 0.f;
            #pragma unroll
            for (int sg = 0; sg < SEGS; sg++)
                s += g_part[((size_t)sg * BB + b) * EE + tid];
            h[r] = s;
        }

        // ---- LayerNorm stats --------------------------------------------
        #pragma unroll
        for (int r = 0; r < R; r++) {
            float s = h[r], q = h[r] * h[r];
            #pragma unroll
            for (int o = 16; o; o >>= 1) {
                s += __shfl_xor_sync(0xffffffffu, s, o);
                q += __shfl_xor_sync(0xffffffffu, q, o);
            }
            if (lane == 0) { reds[r][wid] = s; redq[r][wid] = q; }
        }
        __syncthreads();
        if (tid < R) {
            float s = 0.f, q = 0.f;
            #pragma unroll
            for (int w = 0; w < 8; w++) { s += reds[tid][w]; q += redq[tid][w]; }
            float m   = s * (1.0f / EE);
            float var = q * (1.0f / EE) - m * m;
            mean[tid] = m;
            rstd[tid] = rsqrtf(var + 1e-5f);
        }
        __syncthreads();

        #pragma unroll
        for (int r = 0; r < R; r++) {
            float yv = (h[r] - mean[r]) * rstd[r] * gt + bt;
            act[r][tid] = fmaxf(yv, 0.0f);
        }
        __syncthreads();

        // ---- second matmul ----------------------------------------------
        for (int i = tid; i < nr * L; i += 256) {
            int r = i / L, col = i % L;
            float a = b2[col];
            const float* ar = act[r];
            #pragma unroll 8
            for (int k = 0; k < EE; k++) a += ar[k] * W2[k * L + col];
            lg[r][col] = a;
            int b = DENSE ? (start + r) : rowids[r];
            logits_out[(size_t)b * L + col] = a;
        }
        __syncthreads();

        // ---- argmax + scatter -------------------------------------------
        if (cnt_next && tid < nr) {
            float best = lg[tid][0];
            int   bi   = 0;
            #pragma unroll
            for (int col = 1; col < L; col++) {
                float v = lg[tid][col];
                if (v > best) { best = v; bi = col; }
            }
            int b   = DENSE ? (start + tid) : rowids[tid];
            int nxt = e * L + bi;
            int pos = atomicAdd(&cnt_next[nxt], 1);
            rows_next[nxt * BB + pos] = b;
        }
        __syncthreads();
    }
}

// ---------------------------------------------------------------------------
extern "C" void kernel_launch(void* const* d_in, const int* in_sizes, int n_in,
                              void* d_out, int out_size)
{
    const float* x    = (const float*)d_in[0];
    const float* y    = (const float*)d_in[1];
    const float* l1W1 = (const float*)d_in[2];
    const float* l1g  = (const float*)d_in[3];
    const float* l1b  = (const float*)d_in[4];
    const float* l1W2 = (const float*)d_in[5];
    const float* l1b2 = (const float*)d_in[6];
    const float* l2W1 = (const float*)d_in[7];
    const float* l2g  = (const float*)d_in[8];
    const float* l2b  = (const float*)d_in[9];
    const float* l2W2 = (const float*)d_in[10];
    const float* l2b2 = (const float*)d_in[11];
    const float* l3W1 = (const float*)d_in[12];
    const float* l3g  = (const float*)d_in[13];
    const float* l3b  = (const float*)d_in[14];
    const float* l3W2 = (const float*)d_in[15];
    const float* l3b2 = (const float*)d_in[16];
    float* out = (float*)d_out;

    int* rows2; int* cnt2; int* rows3; int* cnt3;
    cudaGetSymbolAddress((void**)&rows2, g_rows2);
    cudaGetSymbolAddress((void**)&cnt2,  g_cnt2);
    cudaGetSymbolAddress((void**)&rows3, g_rows3);
    cudaGetSymbolAddress((void**)&cnt3,  g_cnt3);

    k_init<<<1, 256>>>();

    // level 1: dense, R=16 (64 chunks), shared W1 (L2 resident)
    k_gemm<16, false, true><<<dim3(64, FSEG, 1), 256>>>(x, nullptr, l1W1,
                                                        nullptr, nullptr);
    k_fin<16, L1C, true><<<dim3(64, 1), 256>>>(nullptr, nullptr,
                                               l1g, l1b, l1W2, l1b2,
                                               out, cnt2, rows2);

    // level 2: 16 experts, mixed features, R=16 (avg 4 chunks/expert)
    k_gemm<16, true, false><<<dim3(4, FSEG, L1C), 256>>>(x, y, l2W1,
                                                         rows2, cnt2);
    k_fin<16, L2C, false><<<dim3(4, L1C), 256>>>(rows2, cnt2,
                                                 l2g, l2b, l2W2, l2b2,
                                                 out + (size_t)BB * L1C,
                                                 cnt3, rows3);

    // level 3: 128 experts, R=8 (avg 1 chunk/expert, slot 1 covers skew)
    k_gemm<8, false, false><<<dim3(2, FSEG, NE3), 256>>>(x, nullptr, l3W1,
                                                         rows3, cnt3);
    k_fin<8, L3C, false><<<dim3(2, NE3), 256>>>(rows3, cnt3,
                                                l3g, l3b, l3W2, l3b2,
                                                out + (size_t)BB * (L1C + L2C),
                                                nullptr, nullptr);
}

// round 7
// speedup vs baseline: 1.0889x; 1.0889x over previous
#include <cuda_runtime.h>

// ---------------------------------------------------------------------------
// MultiLevelClassifier — routed experts, round 4.
//
// R3 post-mortem: R=16 with u64-per-row accs -> 100 regs, occ 20%; and the
// inner loop spent ~2.4 issue slots per FFMA2 (LDS + dup-pack + FFMA2).
//
// R4: register tile RT rows x 4 cols per thread.
//   - weights: one LDG.128 per f (4 consecutive cols) -> 2 packed u64, free
//   - features: stored DUPLICATED in smem as float2(v,v) -> one LDS.64 is
//     the ready f32x2 multiplicand (broadcast across the warp, conflict-free)
//   - inner loop: 1 LDG.128 + RT LDS.64 + 2*RT FFMA2  => 1.6 instr/FFMA2
//   - acc = 2*RT u64 = 16 regs (RT=4) -> ~5 blocks/SM
// Split-K over 8 f-segments into g_part; fin kernels unchanged from R2.
// ---------------------------------------------------------------------------

#define BB   1024
#define FF   1024
#define EE   256
#define L1C  16
#define L2C  8
#define L3C  32
#define NE3  128
#define FSEG 8
#define FS   (FF / FSEG)   // 128

// scratch (device globals — no allocation allowed)
__device__ int   g_cnt2[L1C];
__device__ int   g_cnt3[NE3];
__device__ int   g_rows2[L1C * BB];
__device__ int   g_rows3[NE3 * BB];
__device__ float g_part[FSEG * BB * EE];   // 8 MB split-K partials

// ---- packed f32x2 helpers --------------------------------------------------
__device__ __forceinline__ void fma_f32x2(unsigned long long& d,
                                          unsigned long long a,
                                          unsigned long long b) {
    asm("fma.rn.f32x2 %0, %1, %2, %0;" : "+l"(d) : "l"(a), "l"(b));
}
__device__ __forceinline__ float2 unpack2(unsigned long long v) {
    float2 r;
    asm("mov.b64 {%0, %1}, %2;" : "=f"(r.x), "=f"(r.y) : "l"(v));
    return r;
}

// ---------------------------------------------------------------------------
__global__ void k_init() {
    int t = threadIdx.x;
    if (t < L1C) g_cnt2[t] = 0;
    if (t < NE3) g_cnt3[t] = 0;
}

// ---------------------------------------------------------------------------
// Split-K GEMM. Block (slot, seg, expert), 256 threads.
//   cg = tid & 63  -> columns 4*cg .. 4*cg+3  (LDG.128 weights, coalesced)
//   rg = tid >> 6  -> rows rg*RT .. rg*RT+RT-1   (R = 4*RT rows per block)
// Features cached in smem duplicated: feat[r][f] = (v, v).
// ---------------------------------------------------------------------------
template <int RT, bool MIX, bool DENSE>
__global__ __launch_bounds__(256) void k_gemm(
    const float* __restrict__ fx, const float* __restrict__ fy,
    const float* __restrict__ W1base,          // [NEXP][FF][EE]
    const int* __restrict__ rowlists,
    const int* __restrict__ cnts)
{
    constexpr int R = 4 * RT;
    const int tid  = threadIdx.x;
    const int cg   = tid & 63;
    const int rg   = tid >> 6;
    const int slot = blockIdx.x, nslot = gridDim.x;
    const int seg  = blockIdx.y;
    const int e    = blockIdx.z;
    const int f0   = seg * FS;
    const int cnt  = DENSE ? BB : cnts[e];
    const float* __restrict__ W1 =
        W1base + (size_t)e * FF * EE + (size_t)f0 * EE + 4 * cg;

    __shared__ float2 feat[R][FS];   // duplicated pairs: 8 B per (r,f)

    for (int c = slot; c * R < cnt; c += nslot) {
        const int start = c * R;
        const int nr = min(R, cnt - start);
        const int* rowids = DENSE ? nullptr : (rowlists + e * BB + start);

        // ---- cooperative feature load (write duplicated pairs) ----------
        #pragma unroll
        for (int i = tid; i < R * FS / 4; i += 256) {
            int r  = i / (FS / 4);
            int j  = (i % (FS / 4)) * 4;
            int rr = (r < nr) ? r : 0;
            int b  = DENSE ? (start + rr) : rowids[rr];
            float4 v = *(const float4*)(fx + (size_t)b * FF + f0 + j);
            if (MIX) {
                float4 u = *(const float4*)(fy + (size_t)b * FF + f0 + j);
                v.x = 0.6f * v.x + 0.4f * u.x;
                v.y = 0.6f * v.y + 0.4f * u.y;
                v.z = 0.6f * v.z + 0.4f * u.z;
                v.w = 0.6f * v.w + 0.4f * u.w;
            }
            feat[r][j + 0] = make_float2(v.x, v.x);
            feat[r][j + 1] = make_float2(v.y, v.y);
            feat[r][j + 2] = make_float2(v.z, v.z);
            feat[r][j + 3] = make_float2(v.w, v.w);
        }
        __syncthreads();

        // ---- register-tile GEMM: RT rows x 4 cols -----------------------
        unsigned long long acc[RT][2];
        #pragma unroll
        for (int t = 0; t < RT; t++) { acc[t][0] = 0ull; acc[t][1] = 0ull; }

        #pragma unroll 4
        for (int f = 0; f < FS; f++) {
            // 4 consecutive weight cols: one LDG.128, halves are ready u64s
            ulonglong2 w = *(const ulonglong2*)(W1 + (size_t)f * EE);
            #pragma unroll
            for (int t = 0; t < RT; t++) {
                unsigned long long fv =
                    *(const unsigned long long*)&feat[rg * RT + t][f];
                fma_f32x2(acc[t][0], fv, w.x);
                fma_f32x2(acc[t][1], fv, w.y);
            }
        }

        // ---- write partials (STG.128, 16B-aligned) ----------------------
        #pragma unroll
        for (int t = 0; t < RT; t++) {
            int r = rg * RT + t;
            if (r < nr) {
                int b = DENSE ? (start + r) : rowids[r];
                float2 lo = unpack2(acc[t][0]);
                float2 hi = unpack2(acc[t][1]);
                *(float4*)&g_part[((size_t)seg * BB + b) * EE + 4 * cg] =
                    make_float4(lo.x, lo.y, hi.x, hi.y);
            }
        }
        __syncthreads();
    }
}

// ---------------------------------------------------------------------------
// Finish: reduce FSEG partials -> LN -> ReLU -> x W2 + b2 -> logits,
// argmax -> scatter to next-level routing lists.
// ---------------------------------------------------------------------------
template <int R, int L, bool DENSE>
__global__ __launch_bounds__(256) void k_fin(
    const int* __restrict__ rowlists, const int* __restrict__ cnts,
    const float* __restrict__ gbase, const float* __restrict__ bbase,
    const float* __restrict__ W2base, const float* __restrict__ b2base,
    float* __restrict__ logits_out,
    int* __restrict__ cnt_next, int* __restrict__ rows_next)
{
    const int tid  = threadIdx.x;
    const int slot = blockIdx.x, nslot = gridDim.x;
    const int e    = blockIdx.y;
    const int cnt  = DENSE ? BB : cnts[e];

    const float* __restrict__ gg = gbase  + (size_t)e * EE;
    const float* __restrict__ bv = bbase  + (size_t)e * EE;
    const float* __restrict__ W2 = W2base + (size_t)e * EE * L;
    const float* __restrict__ b2 = b2base + (size_t)e * L;

    __shared__ float act[R][EE];
    __shared__ float reds[R][8], redq[R][8];
    __shared__ float mean[R], rstd[R];
    __shared__ float lg[R][32];

    const int lane = tid & 31, wid = tid >> 5;
    const float gt = gg[tid], bt = bv[tid];

    for (int c = slot; c * R < cnt; c += nslot) {
        const int start = c * R;
        const int nr = min(R, cnt - start);
        const int* rowids = DENSE ? nullptr : (rowlists + e * BB + start);

        // ---- reduce split-K partials ------------------------------------
        float h[R];
        #pragma unroll
        for (int r = 0; r < R; r++) {
            int rr = (r < nr) ? r : 0;
            int b  = DENSE ? (start + rr) : rowids[rr];
            float s = 0.f;
            #pragma unroll
            for (int sg = 0; sg < FSEG; sg++)
                s += g_part[((size_t)sg * BB + b) * EE + tid];
            h[r] = s;
        }

        // ---- LayerNorm stats --------------------------------------------
        #pragma unroll
        for (int r = 0; r < R; r++) {
            float s = h[r], q = h[r] * h[r];
            #pragma unroll
            for (int o = 16; o; o >>= 1) {
                s += __shfl_xor_sync(0xffffffffu, s, o);
                q += __shfl_xor_sync(0xffffffffu, q, o);
            }
            if (lane == 0) { reds[r][wid] = s; redq[r][wid] = q; }
        }
        __syncthreads();
        if (tid < R) {
            float s = 0.f, q = 0.f;
            #pragma unroll
            for (int w = 0; w < 8; w++) { s += reds[tid][w]; q += redq[tid][w]; }
            float m   = s * (1.0f / EE);
            float var = q * (1.0f / EE) - m * m;
            mean[tid] = m;
            rstd[tid] = rsqrtf(var + 1e-5f);
        }
        __syncthreads();

        #pragma unroll
        for (int r = 0; r < R; r++) {
            float yv = (h[r] - mean[r]) * rstd[r] * gt + bt;
            act[r][tid] = fmaxf(yv, 0.0f);
        }
        __syncthreads();

        // ---- second matmul ----------------------------------------------
        for (int i = tid; i < nr * L; i += 256) {
            int r = i / L, col = i % L;
            float a = b2[col];
            const float* ar = act[r];
            #pragma unroll 8
            for (int k = 0; k < EE; k++) a += ar[k] * W2[k * L + col];
            lg[r][col] = a;
            int b = DENSE ? (start + r) : rowids[r];
            logits_out[(size_t)b * L + col] = a;
        }
        __syncthreads();

        // ---- argmax + scatter -------------------------------------------
        if (cnt_next && tid < nr) {
            float best = lg[tid][0];
            int   bi   = 0;
            #pragma unroll
            for (int col = 1; col < L; col++) {
                float v = lg[tid][col];
                if (v > best) { best = v; bi = col; }
            }
            int b   = DENSE ? (start + tid) : rowids[tid];
            int nxt = e * L + bi;
            int pos = atomicAdd(&cnt_next[nxt], 1);
            rows_next[nxt * BB + pos] = b;
        }
        __syncthreads();
    }
}

// ---------------------------------------------------------------------------
extern "C" void kernel_launch(void* const* d_in, const int* in_sizes, int n_in,
                              void* d_out, int out_size)
{
    const float* x    = (const float*)d_in[0];
    const float* y    = (const float*)d_in[1];
    const float* l1W1 = (const float*)d_in[2];
    const float* l1g  = (const float*)d_in[3];
    const float* l1b  = (const float*)d_in[4];
    const float* l1W2 = (const float*)d_in[5];
    const float* l1b2 = (const float*)d_in[6];
    const float* l2W1 = (const float*)d_in[7];
    const float* l2g  = (const float*)d_in[8];
    const float* l2b  = (const float*)d_in[9];
    const float* l2W2 = (const float*)d_in[10];
    const float* l2b2 = (const float*)d_in[11];
    const float* l3W1 = (const float*)d_in[12];
    const float* l3g  = (const float*)d_in[13];
    const float* l3b  = (const float*)d_in[14];
    const float* l3W2 = (const float*)d_in[15];
    const float* l3b2 = (const float*)d_in[16];
    float* out = (float*)d_out;

    int* rows2; int* cnt2; int* rows3; int* cnt3;
    cudaGetSymbolAddress((void**)&rows2, g_rows2);
    cudaGetSymbolAddress((void**)&cnt2,  g_cnt2);
    cudaGetSymbolAddress((void**)&rows3, g_rows3);
    cudaGetSymbolAddress((void**)&cnt3,  g_cnt3);

    k_init<<<1, 256>>>();

    // level 1: dense, RT=4 (R=16), 64 chunks; W1 shared -> L2 resident
    k_gemm<4, false, true><<<dim3(64, FSEG, 1), 256>>>(x, nullptr, l1W1,
                                                       nullptr, nullptr);
    k_fin<16, L1C, true><<<dim3(64, 1), 256>>>(nullptr, nullptr,
                                               l1g, l1b, l1W2, l1b2,
                                               out, cnt2, rows2);

    // level 2: 16 experts, mixed features, RT=4 (R=16), 8 slots for skew
    k_gemm<4, true, false><<<dim3(8, FSEG, L1C), 256>>>(x, y, l2W1,
                                                        rows2, cnt2);
    k_fin<16, L2C, false><<<dim3(8, L1C), 256>>>(rows2, cnt2,
                                                 l2g, l2b, l2W2, l2b2,
                                                 out + (size_t)BB * L1C,
                                                 cnt3, rows3);

    // level 3: 128 experts, RT=2 (R=8)
    k_gemm<2, false, false><<<dim3(2, FSEG, NE3), 256>>>(x, nullptr, l3W1,
                                                         rows3, cnt3);
    k_fin<8, L3C, false><<<dim3(2, NE3), 256>>>(rows3, cnt3,
                                                l3g, l3b, l3W2, l3b2,
                                                out + (size_t)BB * (L1C + L2C),
                                                nullptr, nullptr);
}